// round 5
// baseline (speedup 1.0000x reference)
#include <cuda_runtime.h>
#include <cuda_bf16.h>
#include <math.h>

#define N_ROWS 8192
#define D_DIM  128
#define EK     10           // extended screen dims: 8 feature + 2 aux
#define EROW   12           // padded row length of d_E (float4-aligned)
#define CGX 8
#define CGY 64              // covers tiles_r up to 64 (any split)
#define CROSS_BLOCKS (CGX * CGY)
#define PITCH 132

// ---------------- device scratch ----------------
__device__ float  d_F[2][N_ROWS * D_DIM];   // compacted features (exact recheck)
__device__ float  d_E[2][N_ROWS * EROW];    // extended screen rows
__device__ float  d_rsq[2][N_ROWS];         // full ||x||^2 per compacted row
__device__ int    d_cnt[2];
__device__ float  d_vsum[2][D_DIM];
__device__ double d_acc[4];                 // 0 focal, 1 graph, 2 Snorm0, 3 Snorm1
__device__ double d_cross;
__device__ unsigned d_done;

__device__ __forceinline__ float warp_sum(float v) {
    #pragma unroll
    for (int o = 16; o > 0; o >>= 1) v += __shfl_xor_sync(0xffffffffu, v, o);
    return v;
}

// ---------------- partition + focal + graph + class stats ----------------
__global__ void __launch_bounds__(256) partition_kernel(
    const float* __restrict__ preds,
    const float* __restrict__ targets,
    const float* __restrict__ features,
    const float* __restrict__ gfeat)
{
    __shared__ float s_v[8][D_DIM];
    __shared__ float s_sn[2];
    __shared__ float s_focal, s_graph;
    __shared__ int   s_lab[8];
    __shared__ int   s_base[2];

    int tid = threadIdx.x;
    if (tid == 254) { s_sn[0] = 0.0f; s_sn[1] = 0.0f; }
    if (tid == 255) { s_focal = 0.0f; s_graph = 0.0f; }

    int warp = tid >> 5, lane = tid & 31;
    int i = blockIdx.x * 8 + warp;

    float4 f = *(const float4*)(features + (size_t)i * D_DIM + lane * 4);
    float c  = f.x*f.x + f.y*f.y + f.z*f.z + f.w*f.w;
    float nsq  = warp_sum(c);
    float nsq8 = warp_sum(lane < 2 ? c : 0.0f);   // dims [0,8)

    float tgt = targets[i];
    int lab = (tgt > 0.5f) ? 1 : 0;
    if (lane == 0) s_lab[warp] = lab;

    s_v[warp][lane * 4 + 0] = f.x;
    s_v[warp][lane * 4 + 1] = f.y;
    s_v[warp][lane * 4 + 2] = f.z;
    s_v[warp][lane * 4 + 3] = f.w;
    __syncthreads();

    if (tid == 0) {
        int c1 = 0;
        #pragma unroll
        for (int w = 0; w < 8; ++w) c1 += s_lab[w];
        s_base[0] = atomicAdd(&d_cnt[0], 8 - c1);
        s_base[1] = atomicAdd(&d_cnt[1], c1);
    }
    __syncthreads();

    int rank = 0;
    #pragma unroll
    for (int w = 0; w < 8; ++w) rank += (w < warp && s_lab[w] == lab);
    int idx = s_base[lab] + rank;

    *(float4*)(d_F[lab] + (size_t)idx * D_DIM + lane * 4) = f;
    if (lane == 0) d_rsq[lab][idx] = nsq;

    // extended screen row: a'.b' = ||a8-b8||^2
    {
        float s = (lab == 0) ? -1.41421356237f : 1.41421356237f;
        if (lane < 2) {
            float4 e = make_float4(s*f.x, s*f.y, s*f.z, s*f.w);
            *(float4*)(d_E[lab] + (size_t)idx * EROW + lane * 4) = e;
        }
        if (lane == 2) {
            float4 aux = (lab == 0) ? make_float4(nsq8, 1.0f, 0.0f, 0.0f)
                                    : make_float4(1.0f, nsq8, 0.0f, 0.0f);
            *(float4*)(d_E[lab] + (size_t)idx * EROW + 8) = aux;
        }
    }

    if (lane == 0) atomicAdd(&s_sn[lab], nsq);
    if (lane == 0) {
        float p = preds[i];
        float bce = fmaxf(p, 0.0f) - p * tgt + log1pf(expf(-fabsf(p)));
        float pt = expf(-bce);
        float om = 1.0f - pt;
        atomicAdd(&s_focal, 0.25f * om * om * bce);
    }

    if (i >= 1) {
        const float4 a = *(const float4*)(gfeat + (size_t)i       * D_DIM + lane * 4);
        const float4 b = *(const float4*)(gfeat + (size_t)(i - 1) * D_DIM + lane * 4);
        float dx = a.x - b.x, dy = a.y - b.y, dz = a.z - b.z, dw = a.w - b.w;
        float ds = warp_sum(dx*dx + dy*dy + dz*dz + dw*dw);
        if (lane == 0) atomicAdd(&s_graph, sqrtf(ds));
    }
    __syncthreads();

    {
        int cls = tid >> 7, comp = tid & 127;
        float sum = 0.0f;
        #pragma unroll
        for (int w = 0; w < 8; ++w)
            if (s_lab[w] == cls) sum += s_v[w][comp];
        if (sum != 0.0f) atomicAdd(&d_vsum[cls][comp], sum);
    }
    if (tid == 0) {
        atomicAdd(&d_acc[0], (double)s_focal);
        atomicAdd(&d_acc[1], (double)s_graph);
        atomicAdd(&d_acc[2], (double)s_sn[0]);
        atomicAdd(&d_acc[3], (double)s_sn[1]);
    }
}

// ---------------- cross-label screen GEMM (K=10, acc == sq8) ----------------
__global__ void __launch_bounds__(256, 2) cross_kernel(float* __restrict__ out) {
    __shared__ float As[EK * PITCH];
    __shared__ float Bs[2][EK * PITCH];
    __shared__ float redw[8];
    __shared__ unsigned s_ticket;

    int n0 = d_cnt[0], n1 = d_cnt[1];
    int tiles_r = (n0 + 127) >> 7;
    int tiles_c = (n1 + 127) >> 7;
    int tid = threadIdx.x;
    int tr = blockIdx.y;

    float lsum = 0.0f;

    if (tr < tiles_r) {
        int row0 = tr * 128;
        int ty = tid >> 4, tx = tid & 15;
        int lr = tid >> 1, lc = tid & 1;    // loader: row 0..127, half 0/1

        // ---- A tile: 128 rows x 10 dims, transposed [k][m], loaded once ----
        {
            float4 q0 = make_float4(0,0,0,0), q1 = make_float4(0,0,0,0);
            float2 q2 = make_float2(1e30f, 1.0f);   // class0 pad aux
            if (row0 + lr < n0) {
                const float* E = d_E[0] + (size_t)(row0 + lr) * EROW;
                if (lc == 0) q0 = *(const float4*)(E);
                else { q1 = *(const float4*)(E + 4); q2 = *(const float2*)(E + 8); }
            }
            if (lc == 0) {
                As[0 * PITCH + lr] = q0.x;
                As[1 * PITCH + lr] = q0.y;
                As[2 * PITCH + lr] = q0.z;
                As[3 * PITCH + lr] = q0.w;
            } else {
                As[4 * PITCH + lr] = q1.x;
                As[5 * PITCH + lr] = q1.y;
                As[6 * PITCH + lr] = q1.z;
                As[7 * PITCH + lr] = q1.w;
                As[8 * PITCH + lr] = q2.x;
                As[9 * PITCH + lr] = q2.y;
            }
        }
        int gi0 = row0 + ty * 8;

        // ---- prime double buffer ----
        int tc = blockIdx.x;
        float4 st0 = make_float4(0,0,0,0), st1 = make_float4(0,0,0,0);
        float2 st2 = make_float2(1.0f, 1e30f);      // class1 pad aux
        if (tc < tiles_c) {
            int c0 = tc * 128;
            if (c0 + lr < n1) {
                const float* E = d_E[1] + (size_t)(c0 + lr) * EROW;
                if (lc == 0) st0 = *(const float4*)(E);
                else { st1 = *(const float4*)(E + 4); st2 = *(const float2*)(E + 8); }
            }
        }
        int buf = 0;

        for (; tc < tiles_c; tc += CGX) {
            // commit staged tile
            {
                float* B = Bs[buf];
                if (lc == 0) {
                    B[0 * PITCH + lr] = st0.x;
                    B[1 * PITCH + lr] = st0.y;
                    B[2 * PITCH + lr] = st0.z;
                    B[3 * PITCH + lr] = st0.w;
                } else {
                    B[4 * PITCH + lr] = st1.x;
                    B[5 * PITCH + lr] = st1.y;
                    B[6 * PITCH + lr] = st1.z;
                    B[7 * PITCH + lr] = st1.w;
                    B[8 * PITCH + lr] = st2.x;
                    B[9 * PITCH + lr] = st2.y;
                }
            }
            __syncthreads();

            // prefetch next tile into registers
            int tn = tc + CGX;
            st0 = make_float4(0,0,0,0); st1 = make_float4(0,0,0,0);
            st2 = make_float2(1.0f, 1e30f);
            if (tn < tiles_c) {
                int c0 = tn * 128;
                if (c0 + lr < n1) {
                    const float* E = d_E[1] + (size_t)(c0 + lr) * EROW;
                    if (lc == 0) st0 = *(const float4*)(E);
                    else { st1 = *(const float4*)(E + 4); st2 = *(const float2*)(E + 8); }
                }
            }

            // ---- K=10 GEMM: acc[i][j] == sq8(i,j) (>=1e30 for padding) ----
            float acc[8][8];
            #pragma unroll
            for (int i = 0; i < 8; ++i)
                #pragma unroll
                for (int j = 0; j < 8; ++j) acc[i][j] = 0.0f;

            const float* B = Bs[buf];
            #pragma unroll
            for (int k = 0; k < EK; ++k) {
                float a[8], b[8];
                *(float4*)&a[0] = *(const float4*)(As + k * PITCH + ty * 8);
                *(float4*)&a[4] = *(const float4*)(As + k * PITCH + ty * 8 + 4);
                *(float4*)&b[0] = *(const float4*)(B + k * PITCH + tx * 8);
                *(float4*)&b[4] = *(const float4*)(B + k * PITCH + tx * 8 + 4);
                #pragma unroll
                for (int i = 0; i < 8; ++i)
                    #pragma unroll
                    for (int j = 0; j < 8; ++j)
                        acc[i][j] += a[i] * b[j];
            }

            // ---- screen: min-fold, rare rescan ----
            float m = acc[0][0];
            #pragma unroll
            for (int i = 0; i < 8; ++i)
                #pragma unroll
                for (int j = 0; j < 8; ++j)
                    m = fminf(m, acc[i][j]);

            if (m < 1.5f) {
                int gj0 = tc * 128 + tx * 8;
                #pragma unroll 1
                for (int i = 0; i < 8; ++i) {
                    #pragma unroll 1
                    for (int j = 0; j < 8; ++j) {
                        if (acc[i][j] < 1.5f) {
                            const float* A  = d_F[0] + (size_t)(gi0 + i) * D_DIM;
                            const float* Bf = d_F[1] + (size_t)(gj0 + j) * D_DIM;
                            float dot = 0.0f;
                            for (int d = 0; d < D_DIM; ++d) dot += A[d] * Bf[d];
                            float sq = fmaxf(d_rsq[0][gi0 + i] + d_rsq[1][gj0 + j]
                                             - 2.0f * dot, 0.0f);
                            float t = 1.0f - sqrtf(sq);
                            if (t > 0.0f) lsum += t * t;
                        }
                    }
                }
            }

            buf ^= 1;
        }
    }

    // ---- one cheap reduction per block ----
    lsum = warp_sum(lsum);
    if ((tid & 31) == 0) redw[tid >> 5] = lsum;
    __syncthreads();
    if (tid == 0) {
        float s = 0.0f;
        #pragma unroll
        for (int w = 0; w < 8; ++w) s += redw[w];
        if (s != 0.0f) atomicAdd(&d_cross, (double)s);
    }

    // ---- completion ticket: last block finalizes + resets ----
    __threadfence();
    if (tid == 0) s_ticket = atomicAdd(&d_done, 1u);
    __syncthreads();
    if (s_ticket == CROSS_BLOCKS - 1) {
        __threadfence();
        __shared__ double s[256];
        int cls = tid >> 7, comp = tid & 127;
        double v = (double)d_vsum[cls][comp];
        s[tid] = v * v;
        __syncthreads();
        for (int st = 64; st > 0; st >>= 1) {
            if (comp < st) s[tid] += s[tid + st];
            __syncthreads();
        }
        if (tid == 0) {
            double vn0 = s[0], vn1 = s[128];
            double dn0 = (double)n0, dn1 = (double)n1;
            double same = 2.0 * (dn0 * d_acc[2] - vn0) + 2.0 * (dn1 * d_acc[3] - vn1);
            double NN = (double)N_ROWS * (double)N_ROWS;
            double contrast = (same + 2.0 * d_cross) / NN;
            double focal = d_acc[0] / (double)N_ROWS;
            double graph = 0.1 * d_acc[1] / (double)(N_ROWS - 1);
            out[0] = (float)(focal + contrast + graph);
            d_cnt[0] = 0; d_cnt[1] = 0;
            d_acc[0] = 0.0; d_acc[1] = 0.0; d_acc[2] = 0.0; d_acc[3] = 0.0;
            d_cross = 0.0;
            d_done = 0u;
        }
        d_vsum[cls][comp] = 0.0f;
    }
}

// ---------------- launch ----------------
extern "C" void kernel_launch(void* const* d_in, const int* in_sizes, int n_in,
                              void* d_out, int out_size) {
    const float* preds    = (const float*)d_in[0];
    const float* targets  = (const float*)d_in[1];
    const float* features = (const float*)d_in[2];
    const float* gfeat    = (const float*)d_in[3];
    float* out = (float*)d_out;

    partition_kernel<<<N_ROWS / 8, 256>>>(preds, targets, features, gfeat);
    cross_kernel<<<dim3(CGX, CGY), 256>>>(out);
}

// round 6
// speedup vs baseline: 1.6808x; 1.6808x over previous
#include <cuda_runtime.h>
#include <cuda_bf16.h>
#include <math.h>

#define N_ROWS 8192
#define D_DIM  128
#define EK     10           // screen dims: 8 feature + 2 aux (acc == sq8)
#define EROW   12           // padded d_E row (float4-aligned)
#define CGX 8
#define CGY 64
#define CROSS_BLOCKS (CGX * CGY)
#define PITCH 132

// ---------------- device scratch ----------------
__device__ float  d_F[2][N_ROWS * D_DIM];
__device__ float  d_E[2][N_ROWS * EROW];
__device__ float  d_rsq[2][N_ROWS];
__device__ int    d_cnt[2];
__device__ float  d_vsum[2][D_DIM];
__device__ double d_acc[4];
__device__ double d_cross;
__device__ unsigned d_done;

__device__ __forceinline__ float warp_sum(float v) {
    #pragma unroll
    for (int o = 16; o > 0; o >>= 1) v += __shfl_xor_sync(0xffffffffu, v, o);
    return v;
}

// ---------------- partition + focal + graph + class stats ----------------
__global__ void __launch_bounds__(256) partition_kernel(
    const float* __restrict__ preds,
    const float* __restrict__ targets,
    const float* __restrict__ features,
    const float* __restrict__ gfeat)
{
    __shared__ float s_v[8][D_DIM];
    __shared__ float s_sn[2];
    __shared__ float s_focal, s_graph;
    __shared__ int   s_lab[8];
    __shared__ int   s_base[2];

    int tid = threadIdx.x;
    if (tid == 254) { s_sn[0] = 0.0f; s_sn[1] = 0.0f; }
    if (tid == 255) { s_focal = 0.0f; s_graph = 0.0f; }

    int warp = tid >> 5, lane = tid & 31;
    int i = blockIdx.x * 8 + warp;

    float4 f = *(const float4*)(features + (size_t)i * D_DIM + lane * 4);
    float c  = f.x*f.x + f.y*f.y + f.z*f.z + f.w*f.w;
    float nsq  = warp_sum(c);
    float nsq8 = warp_sum(lane < 2 ? c : 0.0f);

    float tgt = targets[i];
    int lab = (tgt > 0.5f) ? 1 : 0;
    if (lane == 0) s_lab[warp] = lab;

    s_v[warp][lane * 4 + 0] = f.x;
    s_v[warp][lane * 4 + 1] = f.y;
    s_v[warp][lane * 4 + 2] = f.z;
    s_v[warp][lane * 4 + 3] = f.w;
    __syncthreads();

    if (tid == 0) {
        int c1 = 0;
        #pragma unroll
        for (int w = 0; w < 8; ++w) c1 += s_lab[w];
        s_base[0] = atomicAdd(&d_cnt[0], 8 - c1);
        s_base[1] = atomicAdd(&d_cnt[1], c1);
    }
    __syncthreads();

    int rank = 0;
    #pragma unroll
    for (int w = 0; w < 8; ++w) rank += (w < warp && s_lab[w] == lab);
    int idx = s_base[lab] + rank;

    *(float4*)(d_F[lab] + (size_t)idx * D_DIM + lane * 4) = f;
    if (lane == 0) d_rsq[lab][idx] = nsq;

    {   // extended screen row: a'.b' == ||a8-b8||^2
        float s = (lab == 0) ? -1.41421356237f : 1.41421356237f;
        if (lane < 2) {
            float4 e = make_float4(s*f.x, s*f.y, s*f.z, s*f.w);
            *(float4*)(d_E[lab] + (size_t)idx * EROW + lane * 4) = e;
        }
        if (lane == 2) {
            float4 aux = (lab == 0) ? make_float4(nsq8, 1.0f, 0.0f, 0.0f)
                                    : make_float4(1.0f, nsq8, 0.0f, 0.0f);
            *(float4*)(d_E[lab] + (size_t)idx * EROW + 8) = aux;
        }
    }

    if (lane == 0) atomicAdd(&s_sn[lab], nsq);
    if (lane == 0) {
        float p = preds[i];
        float bce = fmaxf(p, 0.0f) - p * tgt + log1pf(expf(-fabsf(p)));
        float pt = expf(-bce);
        float om = 1.0f - pt;
        atomicAdd(&s_focal, 0.25f * om * om * bce);
    }

    if (i >= 1) {
        const float4 a = *(const float4*)(gfeat + (size_t)i       * D_DIM + lane * 4);
        const float4 b = *(const float4*)(gfeat + (size_t)(i - 1) * D_DIM + lane * 4);
        float dx = a.x - b.x, dy = a.y - b.y, dz = a.z - b.z, dw = a.w - b.w;
        float ds = warp_sum(dx*dx + dy*dy + dz*dz + dw*dw);
        if (lane == 0) atomicAdd(&s_graph, sqrtf(ds));
    }
    __syncthreads();

    {
        int cls = tid >> 7, comp = tid & 127;
        float sum = 0.0f;
        #pragma unroll
        for (int w = 0; w < 8; ++w)
            if (s_lab[w] == cls) sum += s_v[w][comp];
        if (sum != 0.0f) atomicAdd(&d_vsum[cls][comp], sum);
    }
    if (tid == 0) {
        atomicAdd(&d_acc[0], (double)s_focal);
        atomicAdd(&d_acc[1], (double)s_graph);
        atomicAdd(&d_acc[2], (double)s_sn[0]);
        atomicAdd(&d_acc[3], (double)s_sn[1]);
    }
}

// exact recheck for a surviving pair; out-of-line keeps hot path clean
__device__ __noinline__ float rare_pair(int gi, int gj) {
    const float* A = d_F[0] + (size_t)gi * D_DIM;
    const float* B = d_F[1] + (size_t)gj * D_DIM;
    float dot = 0.0f;
    #pragma unroll 4
    for (int d = 0; d < D_DIM; ++d) dot += A[d] * B[d];
    float sq = fmaxf(d_rsq[0][gi] + d_rsq[1][gj] - 2.0f * dot, 0.0f);
    float t = 1.0f - sqrtf(sq);
    return (t > 0.0f) ? t * t : 0.0f;
}

// ---------------- cross-label screen GEMM (K=10, acc == sq8) ----------------
__global__ void __launch_bounds__(256, 2) cross_kernel(float* __restrict__ out) {
    __shared__ float As[EK * PITCH];
    __shared__ float Bs[2][EK * PITCH];
    __shared__ float redw[8];
    __shared__ unsigned s_ticket;

    int n0 = d_cnt[0], n1 = d_cnt[1];
    int tiles_r = (n0 + 127) >> 7;
    int tiles_c = (n1 + 127) >> 7;
    int tid = threadIdx.x;
    int tr = blockIdx.y;

    float lsum = 0.0f;

    if (tr < tiles_r) {
        int row0 = tr * 128;
        int ty = tid >> 4, tx = tid & 15;
        int lr = tid >> 1, lc = tid & 1;

        // ---- A tile: 128 x 10, transposed [k][m], loaded once ----
        {
            float4 q0 = make_float4(0,0,0,0), q1 = make_float4(0,0,0,0);
            float2 q2 = make_float2(1e30f, 1.0f);
            if (row0 + lr < n0) {
                const float* E = d_E[0] + (size_t)(row0 + lr) * EROW;
                if (lc == 0) q0 = *(const float4*)(E);
                else { q1 = *(const float4*)(E + 4); q2 = *(const float2*)(E + 8); }
            }
            if (lc == 0) {
                As[0*PITCH+lr]=q0.x; As[1*PITCH+lr]=q0.y;
                As[2*PITCH+lr]=q0.z; As[3*PITCH+lr]=q0.w;
            } else {
                As[4*PITCH+lr]=q1.x; As[5*PITCH+lr]=q1.y;
                As[6*PITCH+lr]=q1.z; As[7*PITCH+lr]=q1.w;
                As[8*PITCH+lr]=q2.x; As[9*PITCH+lr]=q2.y;
            }
        }
        int gi0 = row0 + ty * 8;

        // ---- prime buffer 0 directly ----
        int tc = blockIdx.x;
        if (tc < tiles_c) {
            float4 s0 = make_float4(0,0,0,0), s1 = make_float4(0,0,0,0);
            float2 s2 = make_float2(1.0f, 1e30f);
            int c0 = tc * 128;
            if (c0 + lr < n1) {
                const float* E = d_E[1] + (size_t)(c0 + lr) * EROW;
                if (lc == 0) s0 = *(const float4*)(E);
                else { s1 = *(const float4*)(E + 4); s2 = *(const float2*)(E + 8); }
            }
            float* B = Bs[0];
            if (lc == 0) {
                B[0*PITCH+lr]=s0.x; B[1*PITCH+lr]=s0.y;
                B[2*PITCH+lr]=s0.z; B[3*PITCH+lr]=s0.w;
            } else {
                B[4*PITCH+lr]=s1.x; B[5*PITCH+lr]=s1.y;
                B[6*PITCH+lr]=s1.z; B[7*PITCH+lr]=s1.w;
                B[8*PITCH+lr]=s2.x; B[9*PITCH+lr]=s2.y;
            }
        }
        __syncthreads();

        int buf = 0;
        for (; tc < tiles_c; tc += CGX, buf ^= 1) {
            // stage next tile in regs (LDG overlaps compute below)
            int tn = tc + CGX;
            float4 s0 = make_float4(0,0,0,0), s1 = make_float4(0,0,0,0);
            float2 s2 = make_float2(1.0f, 1e30f);
            if (tn < tiles_c) {
                int c0 = tn * 128;
                if (c0 + lr < n1) {
                    const float* E = d_E[1] + (size_t)(c0 + lr) * EROW;
                    if (lc == 0) s0 = *(const float4*)(E);
                    else { s1 = *(const float4*)(E + 4); s2 = *(const float2*)(E + 8); }
                }
            }

            // ---- K=10 GEMM: acc[i][j] == sq8 ----
            float acc[8][8];
            #pragma unroll
            for (int i = 0; i < 8; ++i)
                #pragma unroll
                for (int j = 0; j < 8; ++j) acc[i][j] = 0.0f;

            const float* B = Bs[buf];
            #pragma unroll
            for (int k = 0; k < EK; ++k) {
                float a[8], b[8];
                *(float4*)&a[0] = *(const float4*)(As + k * PITCH + ty * 8);
                *(float4*)&a[4] = *(const float4*)(As + k * PITCH + ty * 8 + 4);
                *(float4*)&b[0] = *(const float4*)(B + k * PITCH + tx * 8);
                *(float4*)&b[4] = *(const float4*)(B + k * PITCH + tx * 8 + 4);
                #pragma unroll
                for (int i = 0; i < 8; ++i)
                    #pragma unroll
                    for (int j = 0; j < 8; ++j)
                        acc[i][j] += a[i] * b[j];
            }

            // ---- fully-unrolled min-fold (acc stays in regs) ----
            float m = acc[0][0];
            #pragma unroll
            for (int i = 0; i < 8; ++i)
                #pragma unroll
                for (int j = 0; j < 8; ++j)
                    m = fminf(m, acc[i][j]);

            if (m < 1.5f) {
                // fully-unrolled mask build; rare path never indexes acc
                unsigned long long mask = 0ull;
                #pragma unroll
                for (int i = 0; i < 8; ++i)
                    #pragma unroll
                    for (int j = 0; j < 8; ++j)
                        if (acc[i][j] < 1.5f)
                            mask |= 1ull << (i * 8 + j);
                int gj0 = tc * 128 + tx * 8;
                while (mask) {
                    int b = __ffsll((long long)mask) - 1;
                    mask &= mask - 1;
                    lsum += rare_pair(gi0 + (b >> 3), gj0 + (b & 7));
                }
            }

            // commit staged tile, one sync per iteration
            {
                float* Bn = Bs[buf ^ 1];
                if (lc == 0) {
                    Bn[0*PITCH+lr]=s0.x; Bn[1*PITCH+lr]=s0.y;
                    Bn[2*PITCH+lr]=s0.z; Bn[3*PITCH+lr]=s0.w;
                } else {
                    Bn[4*PITCH+lr]=s1.x; Bn[5*PITCH+lr]=s1.y;
                    Bn[6*PITCH+lr]=s1.z; Bn[7*PITCH+lr]=s1.w;
                    Bn[8*PITCH+lr]=s2.x; Bn[9*PITCH+lr]=s2.y;
                }
            }
            __syncthreads();
        }
    }

    // ---- one reduction per block ----
    lsum = warp_sum(lsum);
    if ((tid & 31) == 0) redw[tid >> 5] = lsum;
    __syncthreads();
    if (tid == 0) {
        float s = 0.0f;
        #pragma unroll
        for (int w = 0; w < 8; ++w) s += redw[w];
        if (s != 0.0f) atomicAdd(&d_cross, (double)s);
    }

    // ---- completion ticket: last block finalizes + resets ----
    __threadfence();
    if (tid == 0) s_ticket = atomicAdd(&d_done, 1u);
    __syncthreads();
    if (s_ticket == CROSS_BLOCKS - 1) {
        __threadfence();
        __shared__ double s[256];
        int cls = tid >> 7, comp = tid & 127;
        double v = (double)d_vsum[cls][comp];
        s[tid] = v * v;
        __syncthreads();
        for (int st = 64; st > 0; st >>= 1) {
            if (comp < st) s[tid] += s[tid + st];
            __syncthreads();
        }
        if (tid == 0) {
            double vn0 = s[0], vn1 = s[128];
            double dn0 = (double)n0, dn1 = (double)n1;
            double same = 2.0 * (dn0 * d_acc[2] - vn0) + 2.0 * (dn1 * d_acc[3] - vn1);
            double NN = (double)N_ROWS * (double)N_ROWS;
            double contrast = (same + 2.0 * d_cross) / NN;
            double focal = d_acc[0] / (double)N_ROWS;
            double graph = 0.1 * d_acc[1] / (double)(N_ROWS - 1);
            out[0] = (float)(focal + contrast + graph);
            d_cnt[0] = 0; d_cnt[1] = 0;
            d_acc[0] = 0.0; d_acc[1] = 0.0; d_acc[2] = 0.0; d_acc[3] = 0.0;
            d_cross = 0.0;
            d_done = 0u;
        }
        d_vsum[cls][comp] = 0.0f;
    }
}

// ---------------- launch ----------------
extern "C" void kernel_launch(void* const* d_in, const int* in_sizes, int n_in,
                              void* d_out, int out_size) {
    const float* preds    = (const float*)d_in[0];
    const float* targets  = (const float*)d_in[1];
    const float* features = (const float*)d_in[2];
    const float* gfeat    = (const float*)d_in[3];
    float* out = (float*)d_out;

    partition_kernel<<<N_ROWS / 8, 256>>>(preds, targets, features, gfeat);
    cross_kernel<<<dim3(CGX, CGY), 256>>>(out);
}